// round 15
// baseline (speedup 1.0000x reference)
#include <cuda_runtime.h>
#include <math.h>
#include <stdint.h>

#define BATCH   2
#define SEQ     2048
#define DMODEL  1024
#define NHEADS  16
#define HDIM    64
#define MROWS   (BATCH * SEQ)   /* 4096 */
#define SOFT_SCALE 0.18033688011112042f   /* 0.125 * log2(e) */

/* Scratch (allocation-free rule: __device__ globals). */
static __device__ float g_q[MROWS * DMODEL];
static __device__ float g_k[MROWS * DMODEL];
static __device__ float g_v[MROWS * DMODEL];
static __device__ float g_att[MROWS * DMODEL];
static __device__ float g_xt[MROWS * DMODEL];           /* tf32-rounded x  */
static __device__ float g_wq[DMODEL * DMODEL];
static __device__ float g_wk[DMODEL * DMODEL];
static __device__ float g_wv[DMODEL * DMODEL];
static __device__ float g_wo[DMODEL * DMODEL];

__device__ __forceinline__ uint32_t f2tf32(float f) {
    uint32_t r;
    asm("cvt.rna.tf32.f32 %0, %1;" : "=r"(r) : "f"(f));
    return r;
}
__device__ __forceinline__ float f2tf32f(float f) {
    return __uint_as_float(f2tf32(f));
}

__device__ __forceinline__ void mma_tf32(float c[4],
    uint32_t a0, uint32_t a1, uint32_t a2, uint32_t a3,
    uint32_t b0, uint32_t b1)
{
    asm volatile(
        "mma.sync.aligned.m16n8k8.row.col.f32.tf32.tf32.f32 "
        "{%0,%1,%2,%3}, {%4,%5,%6,%7}, {%8,%9}, {%0,%1,%2,%3};"
        : "+f"(c[0]), "+f"(c[1]), "+f"(c[2]), "+f"(c[3])
        : "r"(a0), "r"(a1), "r"(a2), "r"(a3), "r"(b0), "r"(b1));
}

__device__ __forceinline__ void cp16(uint32_t dst_smem, const void* src) {
    asm volatile("cp.async.cg.shared.global [%0], [%1], 16;"
                 :: "r"(dst_smem), "l"(src));
}
__device__ __forceinline__ void cp_commit() { asm volatile("cp.async.commit_group;"); }
__device__ __forceinline__ void cp_wait0()  { asm volatile("cp.async.wait_group 0;"); }
__device__ __forceinline__ void cp_wait1()  { asm volatile("cp.async.wait_group 1;"); }
__device__ __forceinline__ uint32_t smem_u32(const void* p) {
    return (uint32_t)__cvta_generic_to_shared(p);
}

/* ================================================================== */
/* Prep: round x and all W to tf32 values (exact mma inputs later).   */
/* ================================================================== */
__global__ __launch_bounds__(256) void round_prep_kernel(
    const float* __restrict__ x,
    const float* __restrict__ Wq, const float* __restrict__ Wk,
    const float* __restrict__ Wv, const float* __restrict__ Wo)
{
    const int seg = blockIdx.y;
    const float* src;
    float* dst;
    const int M1 = DMODEL * DMODEL;   /* 1M floats */
    if (seg < 4)      { src = x  + (size_t)seg * M1; dst = g_xt + (size_t)seg * M1; }
    else if (seg == 4){ src = Wq; dst = g_wq; }
    else if (seg == 5){ src = Wk; dst = g_wk; }
    else if (seg == 6){ src = Wv; dst = g_wv; }
    else              { src = Wo; dst = g_wo; }

    const int idx = blockIdx.x * blockDim.x + threadIdx.x;
    float4 v = ((const float4*)src)[idx];
    v.x = f2tf32f(v.x); v.y = f2tf32f(v.y);
    v.z = f2tf32f(v.z); v.w = f2tf32f(v.w);
    ((float4*)dst)[idx] = v;
}

/* ================================================================== */
/* TF32 GEMM v6: 3-stage cp.async (wait_group 1 steady state, ONE     */
/* barrier per iter), CTA 128x256, 256 thr, warp 64x64.               */
/* Stage audit: issue(it+2) -> stage (it+2)%3 == (it-1)%3, last read  */
/* in compute(it-1), completed before end-of-(it-1) barrier.          */
/* wait1 at end of iter it leaves tile it+2 in flight, it+1 ready.    */
/* ASTR=20 / BSTR=264: conflict-free frag loads (R8-proven).          */
/* Dynamic smem: 3*(128*20 + 16*264)*4 = 81408 B.                     */
/* ================================================================== */
#define GM 128
#define GN 256
#define GK 16
#define ASTR 20
#define BSTR 264
#define STG 3
#define A_STAGE (GM * ASTR)                 /* 2560 floats */
#define B_STAGE (GK * BSTR)                 /* 4224 floats */
#define GEMM_DSMB (STG * (A_STAGE + B_STAGE) * 4)   /* 81408 B */

template<bool ROUND_OUT>
__device__ __forceinline__ void gemm_body_ca(
    const float* __restrict__ A, const float* __restrict__ W,
    const float* __restrict__ bias, float* __restrict__ C,
    int M, int N, int K, int bx, int by)
{
    extern __shared__ float dsm[];
    float* AsB = dsm;                       /* [STG][GM][ASTR] */
    float* BsB = dsm + STG * A_STAGE;       /* [STG][GK][BSTR] */

    const int tid  = threadIdx.x;
    const int warp = tid >> 5;
    const int lane = tid & 31;
    const int g = lane >> 2;
    const int t = lane & 3;

    const int wm = (warp & 1) * 64;
    const int wn = (warp >> 1) * 64;

    const int brow0 = by * GM;
    const int bcol0 = bx * GN;

    const int arow0 = tid >> 2;          /* 0..63  */
    const int ka    = (tid & 3) * 4;     /* 0,4,8,12 */
    const int browb = tid >> 6;          /* 0..3 */
    const int colb  = (tid & 63) * 4;    /* 0..252 */

    float acc[4][8][4];
#pragma unroll
    for (int mt = 0; mt < 4; mt++)
#pragma unroll
        for (int nt = 0; nt < 8; nt++)
#pragma unroll
            for (int i = 0; i < 4; i++) acc[mt][nt][i] = 0.0f;

    const float* Abase = A + (size_t)brow0 * K;
    const float* Wbase = W + bcol0;

    /* prologue: issue tiles 0 and 1; wait for tile 0 */
#pragma unroll
    for (int p = 0; p < 2; p++) {
        const int k0 = p * GK;
        float* Asp = AsB + p * A_STAGE;
        float* Bsp = BsB + p * B_STAGE;
        cp16(smem_u32(Asp + (arow0     ) * ASTR + ka), Abase + (size_t)(arow0     ) * K + k0 + ka);
        cp16(smem_u32(Asp + (arow0 + 64) * ASTR + ka), Abase + (size_t)(arow0 + 64) * K + k0 + ka);
#pragma unroll
        for (int j = 0; j < 4; j++)
            cp16(smem_u32(Bsp + (browb + 4 * j) * BSTR + colb),
                 Wbase + (size_t)(k0 + browb + 4 * j) * N + colb);
        cp_commit();
    }
    cp_wait1();
    __syncthreads();

    const int NIT = K / GK;   /* 64 */
    for (int it = 0; it < NIT; it++) {
        const int buf = it % STG;
        const float* Asb = AsB + buf * A_STAGE;
        const float* Bsb = BsB + buf * B_STAGE;

        /* issue tile it+2 into stage (it+2)%STG (safe: see audit) */
        if (it + 2 < NIT) {
            const int nb = (it + 2) % STG;
            const int k0 = (it + 2) * GK;
            float* Asn = AsB + nb * A_STAGE;
            float* Bsn = BsB + nb * B_STAGE;
            cp16(smem_u32(Asn + (arow0     ) * ASTR + ka), Abase + (size_t)(arow0     ) * K + k0 + ka);
            cp16(smem_u32(Asn + (arow0 + 64) * ASTR + ka), Abase + (size_t)(arow0 + 64) * K + k0 + ka);
#pragma unroll
            for (int j = 0; j < 4; j++)
                cp16(smem_u32(Bsn + (browb + 4 * j) * BSTR + colb),
                     Wbase + (size_t)(k0 + browb + 4 * j) * N + colb);
            cp_commit();
        }

#pragma unroll
        for (int kk = 0; kk < GK; kk += 8) {
            uint32_t af[4][4];
            uint32_t bf[8][2];
#pragma unroll
            for (int mt = 0; mt < 4; mt++) {
                const int m0 = wm + mt * 16;
                af[mt][0] = __float_as_uint(Asb[(m0 + g    ) * ASTR + kk + t    ]);
                af[mt][1] = __float_as_uint(Asb[(m0 + 8 + g) * ASTR + kk + t    ]);
                af[mt][2] = __float_as_uint(Asb[(m0 + g    ) * ASTR + kk + 4 + t]);
                af[mt][3] = __float_as_uint(Asb[(m0 + 8 + g) * ASTR + kk + 4 + t]);
            }
#pragma unroll
            for (int nt = 0; nt < 8; nt++) {
                const int n0 = wn + nt * 8;
                bf[nt][0] = __float_as_uint(Bsb[(kk + t    ) * BSTR + n0 + g]);
                bf[nt][1] = __float_as_uint(Bsb[(kk + 4 + t) * BSTR + n0 + g]);
            }
#pragma unroll
            for (int mt = 0; mt < 4; mt++)
#pragma unroll
                for (int nt = 0; nt < 8; nt++)
                    mma_tf32(acc[mt][nt],
                             af[mt][0], af[mt][1], af[mt][2], af[mt][3],
                             bf[nt][0], bf[nt][1]);
        }

        if (it + 1 < NIT) {
            if (it + 2 < NIT) cp_wait1(); else cp_wait0();
            __syncthreads();
        }
    }

    /* epilogue */
#pragma unroll
    for (int mt = 0; mt < 4; mt++) {
#pragma unroll
        for (int nt = 0; nt < 8; nt++) {
            const int row = brow0 + wm + mt * 16 + g;
            const int col = bcol0 + wn + nt * 8 + t * 2;
            const float b0 = bias[col];
            const float b1 = bias[col + 1];
            float2 r0, r1;
            r0.x = acc[mt][nt][0] + b0;
            r0.y = acc[mt][nt][1] + b1;
            r1.x = acc[mt][nt][2] + b0;
            r1.y = acc[mt][nt][3] + b1;
            if (ROUND_OUT) {
                r0.x = f2tf32f(r0.x); r0.y = f2tf32f(r0.y);
                r1.x = f2tf32f(r1.x); r1.y = f2tf32f(r1.y);
            }
            *(float2*)(C + (size_t)row * N + col)       = r0;
            *(float2*)(C + (size_t)(row + 8) * N + col) = r1;
        }
    }
}

/* fused QKV via blockIdx.z */
__global__ __launch_bounds__(256) void gemm_qkv_kernel(
    const float* __restrict__ bq, const float* __restrict__ bk,
    const float* __restrict__ bv)
{
    const float* W; const float* bias; float* C;
    if (blockIdx.z == 0)      { W = g_wq; bias = bq; C = g_q; }
    else if (blockIdx.z == 1) { W = g_wk; bias = bk; C = g_k; }
    else                      { W = g_wv; bias = bv; C = g_v; }
    gemm_body_ca<true>(g_xt, W, bias, C, MROWS, DMODEL, DMODEL,
                       blockIdx.x, blockIdx.y);
}

__global__ __launch_bounds__(256) void gemm_ca_plain_kernel(
    const float* __restrict__ A, const float* __restrict__ W,
    const float* __restrict__ bias, float* __restrict__ C,
    int M, int N, int K)
{
    gemm_body_ca<false>(A, W, bias, C, M, N, K, blockIdx.x, blockIdx.y);
}

/* ================================================================== */
/* Tensor-core flash attention (R14, unchanged): 64-key staged tiles, */
/* two 32-key compute halves, static-max softmax, cp.async staging.   */
/* Dynamic smem (88 KB): Ks[2][64][68] | Vs[2][64][72] | Ps[8][16][36]*/
/* ================================================================== */
#define QT   128
#define KVT  64
#define KHALF 32
#define KSTR 68
#define VSTR 72
#define PSTR 36
#define KS_U32 (2 * KVT * KSTR)            /* 8704  u32 */
#define VS_U32 (2 * KVT * VSTR)            /* 9216  u32 */
#define PS_U32 (8 * 16 * PSTR)             /* 4608  u32 */
#define ATT_DSMB ((KS_U32 + VS_U32 + PS_U32) * 4)   /* 90112 B */

__global__ __launch_bounds__(256) void attn_mma_kernel(
    const float* __restrict__ Q, const float* __restrict__ K,
    const float* __restrict__ V, float* __restrict__ O)
{
    extern __shared__ uint32_t dsm_att[];
    uint32_t* sKs = dsm_att;
    uint32_t* sVs = dsm_att + KS_U32;
    uint32_t* sPs = dsm_att + KS_U32 + VS_U32;

    const int tid  = threadIdx.x;
    const int warp = tid >> 5;
    const int lane = tid & 31;
    const int g = lane >> 2;
    const int t = lane & 3;
    const int bh = blockIdx.y;
    const int b  = bh / NHEADS;
    const int h  = bh % NHEADS;
    const int q0 = blockIdx.x * QT + warp * 16;

    const float* qbase = Q + (size_t)(b * SEQ + q0) * DMODEL + h * HDIM;
    uint32_t qa[8][4];
#pragma unroll
    for (int kk = 0; kk < 8; kk++) {
        qa[kk][0] = f2tf32(qbase[(size_t)g       * DMODEL + kk * 8 + t    ] * SOFT_SCALE);
        qa[kk][1] = f2tf32(qbase[(size_t)(g + 8) * DMODEL + kk * 8 + t    ] * SOFT_SCALE);
        qa[kk][2] = f2tf32(qbase[(size_t)g       * DMODEL + kk * 8 + 4 + t] * SOFT_SCALE);
        qa[kk][3] = f2tf32(qbase[(size_t)(g + 8) * DMODEL + kk * 8 + 4 + t] * SOFT_SCALE);
    }

    float of[8][4];
#pragma unroll
    for (int dt = 0; dt < 8; dt++)
#pragma unroll
        for (int i = 0; i < 4; i++) of[dt][i] = 0.0f;
    float l0 = 0.0f, l1 = 0.0f;

    const float* kbase = K + (size_t)b * SEQ * DMODEL + h * HDIM;
    const float* vbase = V + (size_t)b * SEQ * DMODEL + h * HDIM;

    const int dg = (tid & 15) << 2;

    {
#pragma unroll
        for (int i = 0; i < 4; i++) {
            const int key = (tid + i * 256) >> 4;
            const size_t go = (size_t)key * DMODEL + dg;
            cp16(smem_u32(&sKs[(size_t)key * KSTR + dg]), kbase + go);
            cp16(smem_u32(&sVs[(size_t)key * VSTR + dg]), vbase + go);
        }
        cp_commit();
        cp_wait0();
        __syncthreads();
    }

    const int NTILE = SEQ / KVT;   /* 32 */
    for (int it = 0; it < NTILE; it++) {
        const int buf = it & 1;
        uint32_t* Kb = sKs + buf * KVT * KSTR;
        uint32_t* Vb = sVs + buf * KVT * VSTR;

        if (it + 1 < NTILE) {
            const int nb = buf ^ 1;
            uint32_t* Kn = sKs + nb * KVT * KSTR;
            uint32_t* Vn = sVs + nb * KVT * VSTR;
            const size_t base = (size_t)(it + 1) * KVT * DMODEL;
#pragma unroll
            for (int i = 0; i < 4; i++) {
                const int key = (tid + i * 256) >> 4;
                const size_t go = base + (size_t)key * DMODEL + dg;
                cp16(smem_u32(&Kn[(size_t)key * KSTR + dg]), kbase + go);
                cp16(smem_u32(&Vn[(size_t)key * VSTR + dg]), vbase + go);
            }
            cp_commit();
        }

#pragma unroll
        for (int hf = 0; hf < 2; hf++) {
            const uint32_t* Kh = Kb + hf * KHALF * KSTR;
            const uint32_t* Vh = Vb + hf * KHALF * VSTR;

            float sc[4][4];
#pragma unroll
            for (int nt = 0; nt < 4; nt++)
#pragma unroll
                for (int i = 0; i < 4; i++) sc[nt][i] = 0.0f;
#pragma unroll
            for (int kk = 0; kk < 8; kk++) {
#pragma unroll
                for (int nt = 0; nt < 4; nt++) {
                    const uint32_t b0 = Kh[(nt * 8 + g) * KSTR + kk * 8 + t];
                    const uint32_t b1 = Kh[(nt * 8 + g) * KSTR + kk * 8 + 4 + t];
                    mma_tf32(sc[nt], qa[kk][0], qa[kk][1], qa[kk][2], qa[kk][3], b0, b1);
                }
            }

            __syncwarp();

#pragma unroll
            for (int nt = 0; nt < 4; nt++) {
                const float p0 = exp2f(sc[nt][0]);
                const float p1 = exp2f(sc[nt][1]);
                const float p2 = exp2f(sc[nt][2]);
                const float p3 = exp2f(sc[nt][3]);
                l0 += p0 + p1;
                l1 += p2 + p3;
                uint2 lo, hi;
                lo.x = f2tf32(p0); lo.y = f2tf32(p1);
                hi.x = f2tf32(p2); hi.y = f2tf32(p3);
                *(uint2*)&sPs[(warp * 16 + g    ) * PSTR + nt * 8 + 2 * t] = lo;
                *(uint2*)&sPs[(warp * 16 + g + 8) * PSTR + nt * 8 + 2 * t] = hi;
            }
            __syncwarp();

#pragma unroll
            for (int kk = 0; kk < 4; kk++) {
                const uint32_t pa0 = sPs[(warp * 16 + g    ) * PSTR + kk * 8 + t];
                const uint32_t pa1 = sPs[(warp * 16 + g + 8) * PSTR + kk * 8 + t];
                const uint32_t pa2 = sPs[(warp * 16 + g    ) * PSTR + kk * 8 + 4 + t];
                const uint32_t pa3 = sPs[(warp * 16 + g + 8) * PSTR + kk * 8 + 4 + t];
#pragma unroll
                for (int dt = 0; dt < 8; dt++) {
                    const uint32_t b0 = Vh[(kk * 8 + t    ) * VSTR + dt * 8 + g];
                    const uint32_t b1 = Vh[(kk * 8 + 4 + t) * VSTR + dt * 8 + g];
                    mma_tf32(of[dt], pa0, pa1, pa2, pa3, b0, b1);
                }
            }
        }

        if (it + 1 < NTILE) {
            cp_wait0();
            __syncthreads();
        }
    }

    l0 += __shfl_xor_sync(0xffffffffu, l0, 1);
    l0 += __shfl_xor_sync(0xffffffffu, l0, 2);
    l1 += __shfl_xor_sync(0xffffffffu, l1, 1);
    l1 += __shfl_xor_sync(0xffffffffu, l1, 2);

    const float inv0 = 1.0f / l0;
    const float inv1 = 1.0f / l1;
    float* ob = O + (size_t)(b * SEQ + q0) * DMODEL + h * HDIM;
#pragma unroll
    for (int dt = 0; dt < 8; dt++) {
        float2 r0, r1;
        r0.x = f2tf32f(of[dt][0] * inv0); r0.y = f2tf32f(of[dt][1] * inv0);
        r1.x = f2tf32f(of[dt][2] * inv1); r1.y = f2tf32f(of[dt][3] * inv1);
        *(float2*)(ob + (size_t)g       * DMODEL + dt * 8 + 2 * t) = r0;
        *(float2*)(ob + (size_t)(g + 8) * DMODEL + dt * 8 + 2 * t) = r1;
    }
}

/* ------------------------------------------------------------------ */
extern "C" void kernel_launch(void* const* d_in, const int* in_sizes, int n_in,
                              void* d_out, int out_size)
{
    const float* x  = (const float*)d_in[0];
    const float* Wq = (const float*)d_in[1];
    const float* bq = (const float*)d_in[2];
    const float* Wk = (const float*)d_in[3];
    const float* bk = (const float*)d_in[4];
    const float* Wv = (const float*)d_in[5];
    const float* bv = (const float*)d_in[6];
    const float* Wo = (const float*)d_in[7];
    const float* bo = (const float*)d_in[8];
    float* out = (float*)d_out;

    float *q, *k, *v, *att, *wo;
    cudaGetSymbolAddress((void**)&q,   g_q);
    cudaGetSymbolAddress((void**)&k,   g_k);
    cudaGetSymbolAddress((void**)&v,   g_v);
    cudaGetSymbolAddress((void**)&att, g_att);
    cudaGetSymbolAddress((void**)&wo,  g_wo);

    cudaFuncSetAttribute(gemm_qkv_kernel,
        cudaFuncAttributeMaxDynamicSharedMemorySize, GEMM_DSMB);
    cudaFuncSetAttribute(gemm_ca_plain_kernel,
        cudaFuncAttributeMaxDynamicSharedMemorySize, GEMM_DSMB);
    cudaFuncSetAttribute(attn_mma_kernel,
        cudaFuncAttributeMaxDynamicSharedMemorySize, ATT_DSMB);

    /* prep: round x + all W to tf32 values */
    dim3 gprep(DMODEL * DMODEL / 4 / 256, 8);   /* (1024, 8) */
    round_prep_kernel<<<gprep, 256>>>(x, Wq, Wk, Wv, Wo);

    /* fused QKV: (4, 32, 3) = 384 CTAs */
    dim3 gqkv(DMODEL / GN, MROWS / GM, 3);
    gemm_qkv_kernel<<<gqkv, 256, GEMM_DSMB>>>(bq, bk, bv);

    dim3 gattn(SEQ / QT, BATCH * NHEADS);  /* (16, 32) */
    attn_mma_kernel<<<gattn, 256, ATT_DSMB>>>(q, k, v, att);

    dim3 gproj(DMODEL / GN, MROWS / GM);   /* (4, 32) = 128 CTAs */
    gemm_ca_plain_kernel<<<gproj, 256, GEMM_DSMB>>>(att, wo, bo, out, MROWS, DMODEL, DMODEL);
}

// round 16
// speedup vs baseline: 1.0194x; 1.0194x over previous
#include <cuda_runtime.h>
#include <math.h>
#include <stdint.h>

#define BATCH   2
#define SEQ     2048
#define DMODEL  1024
#define NHEADS  16
#define HDIM    64
#define MROWS   (BATCH * SEQ)   /* 4096 */
#define SOFT_SCALE 0.18033688011112042f   /* 0.125 * log2(e) */

/* Scratch (allocation-free rule: __device__ globals). */
static __device__ float g_q[MROWS * DMODEL];
static __device__ float g_k[MROWS * DMODEL];
static __device__ float g_v[MROWS * DMODEL];
static __device__ float g_att[MROWS * DMODEL];
static __device__ float g_xt[MROWS * DMODEL];           /* tf32-rounded x  */
static __device__ float g_wq[DMODEL * DMODEL];
static __device__ float g_wk[DMODEL * DMODEL];
static __device__ float g_wv[DMODEL * DMODEL];
static __device__ float g_wo[DMODEL * DMODEL];

__device__ __forceinline__ uint32_t f2tf32(float f) {
    uint32_t r;
    asm("cvt.rna.tf32.f32 %0, %1;" : "=r"(r) : "f"(f));
    return r;
}
__device__ __forceinline__ float f2tf32f(float f) {
    return __uint_as_float(f2tf32(f));
}

__device__ __forceinline__ void mma_tf32(float c[4],
    uint32_t a0, uint32_t a1, uint32_t a2, uint32_t a3,
    uint32_t b0, uint32_t b1)
{
    asm volatile(
        "mma.sync.aligned.m16n8k8.row.col.f32.tf32.tf32.f32 "
        "{%0,%1,%2,%3}, {%4,%5,%6,%7}, {%8,%9}, {%0,%1,%2,%3};"
        : "+f"(c[0]), "+f"(c[1]), "+f"(c[2]), "+f"(c[3])
        : "r"(a0), "r"(a1), "r"(a2), "r"(a3), "r"(b0), "r"(b1));
}

__device__ __forceinline__ void cp16(uint32_t dst_smem, const void* src) {
    asm volatile("cp.async.cg.shared.global [%0], [%1], 16;"
                 :: "r"(dst_smem), "l"(src));
}
__device__ __forceinline__ void cp_commit() { asm volatile("cp.async.commit_group;"); }
__device__ __forceinline__ void cp_wait0()  { asm volatile("cp.async.wait_group 0;"); }
__device__ __forceinline__ uint32_t smem_u32(const void* p) {
    return (uint32_t)__cvta_generic_to_shared(p);
}

/* ================================================================== */
/* Prep: round x and all W to tf32 values (exact mma inputs later).   */
/* ================================================================== */
__global__ __launch_bounds__(256) void round_prep_kernel(
    const float* __restrict__ x,
    const float* __restrict__ Wq, const float* __restrict__ Wk,
    const float* __restrict__ Wv, const float* __restrict__ Wo)
{
    const int seg = blockIdx.y;
    const float* src;
    float* dst;
    const int M1 = DMODEL * DMODEL;   /* 1M floats */
    if (seg < 4)      { src = x  + (size_t)seg * M1; dst = g_xt + (size_t)seg * M1; }
    else if (seg == 4){ src = Wq; dst = g_wq; }
    else if (seg == 5){ src = Wk; dst = g_wk; }
    else if (seg == 6){ src = Wv; dst = g_wv; }
    else              { src = Wo; dst = g_wo; }

    const int idx = blockIdx.x * blockDim.x + threadIdx.x;
    float4 v = ((const float4*)src)[idx];
    v.x = f2tf32f(v.x); v.y = f2tf32f(v.y);
    v.z = f2tf32f(v.z); v.w = f2tf32f(v.w);
    ((float4*)dst)[idx] = v;
}

/* ================================================================== */
/* TF32 GEMM v7: CTA 128x128 with FOUR warps (128 thr), warp 64x64.   */
/* Same per-warp MMA chain as the proven R8 kernel (32 MMA per kk),   */
/* but ~30K regs/CTA -> 2 independent CTAs per SM (decorrelated        */
/* stalls, no shared barrier between them). 2-stage cp.async.         */
/* ASTR=20: af banks 20g+t distinct. BSTR=136: bf banks 8t+n0+g       */
/* distinct. All cp.async dsts 16B-aligned (80B / 544B rows).         */
/* ================================================================== */
#define GM 128
#define GN 128
#define GK 16
#define ASTR 20
#define BSTR 136

template<bool ROUND_OUT>
__device__ __forceinline__ void gemm_body_ca(
    const float* __restrict__ A, const float* __restrict__ W,
    const float* __restrict__ bias, float* __restrict__ C,
    int M, int N, int K, int bx, int by)
{
    __shared__ float As[2][GM][ASTR];
    __shared__ float Bs[2][GK][BSTR];

    const int tid  = threadIdx.x;
    const int warp = tid >> 5;
    const int lane = tid & 31;
    const int g = lane >> 2;
    const int t = lane & 3;

    const int wm = (warp & 1) * 64;
    const int wn = (warp >> 1) * 64;

    const int brow0 = by * GM;
    const int bcol0 = bx * GN;

    /* cp.async maps (128 threads):
       A 128x16 = 512 chunks -> 4/thread ; B 16x128 = 512 -> 4/thread */
    const int arow = tid >> 2;            /* base rows 0..31, +32*i  */
    const int ka   = (tid & 3) * 4;
    const int brow = tid >> 5;            /* base rows 0..3, +4*i    */
    const int colb = (lane) * 4;          /* 0..124 */

    float acc[4][8][4];
#pragma unroll
    for (int mt = 0; mt < 4; mt++)
#pragma unroll
        for (int nt = 0; nt < 8; nt++)
#pragma unroll
            for (int i = 0; i < 4; i++) acc[mt][nt][i] = 0.0f;

    const float* Abase = A + (size_t)brow0 * K;
    const float* Wbase = W + bcol0;

    /* prologue: tile 0 */
    {
#pragma unroll
        for (int i = 0; i < 4; i++) {
            const int r = arow + i * 32;
            cp16(smem_u32(&As[0][r][ka]), Abase + (size_t)r * K + ka);
        }
#pragma unroll
        for (int i = 0; i < 4; i++) {
            const int r = brow + i * 4;
            cp16(smem_u32(&Bs[0][r][colb]), Wbase + (size_t)r * N + colb);
        }
        cp_commit();
        cp_wait0();
        __syncthreads();
    }

    const int NIT = K / GK;   /* 64 */
    for (int it = 0; it < NIT; it++) {
        const int buf = it & 1;

        if (it + 1 < NIT) {
            const int nb = buf ^ 1;
            const int k0 = (it + 1) * GK;
#pragma unroll
            for (int i = 0; i < 4; i++) {
                const int r = arow + i * 32;
                cp16(smem_u32(&As[nb][r][ka]), Abase + (size_t)r * K + k0 + ka);
            }
#pragma unroll
            for (int i = 0; i < 4; i++) {
                const int r = brow + i * 4;
                cp16(smem_u32(&Bs[nb][r][colb]), Wbase + (size_t)(k0 + r) * N + colb);
            }
            cp_commit();
        }

#pragma unroll
        for (int kk = 0; kk < GK; kk += 8) {
            uint32_t af[4][4];
            uint32_t bf[8][2];
#pragma unroll
            for (int mt = 0; mt < 4; mt++) {
                const int m0 = wm + mt * 16;
                af[mt][0] = __float_as_uint(As[buf][m0 + g    ][kk + t    ]);
                af[mt][1] = __float_as_uint(As[buf][m0 + 8 + g][kk + t    ]);
                af[mt][2] = __float_as_uint(As[buf][m0 + g    ][kk + 4 + t]);
                af[mt][3] = __float_as_uint(As[buf][m0 + 8 + g][kk + 4 + t]);
            }
#pragma unroll
            for (int nt = 0; nt < 8; nt++) {
                const int n0 = wn + nt * 8;
                bf[nt][0] = __float_as_uint(Bs[buf][kk + t    ][n0 + g]);
                bf[nt][1] = __float_as_uint(Bs[buf][kk + 4 + t][n0 + g]);
            }
#pragma unroll
            for (int mt = 0; mt < 4; mt++)
#pragma unroll
                for (int nt = 0; nt < 8; nt++)
                    mma_tf32(acc[mt][nt],
                             af[mt][0], af[mt][1], af[mt][2], af[mt][3],
                             bf[nt][0], bf[nt][1]);
        }

        if (it + 1 < NIT) {
            cp_wait0();
            __syncthreads();
        }
    }

    /* epilogue */
#pragma unroll
    for (int mt = 0; mt < 4; mt++) {
#pragma unroll
        for (int nt = 0; nt < 8; nt++) {
            const int row = brow0 + wm + mt * 16 + g;
            const int col = bcol0 + wn + nt * 8 + t * 2;
            const float b0 = bias[col];
            const float b1 = bias[col + 1];
            float2 r0, r1;
            r0.x = acc[mt][nt][0] + b0;
            r0.y = acc[mt][nt][1] + b1;
            r1.x = acc[mt][nt][2] + b0;
            r1.y = acc[mt][nt][3] + b1;
            if (ROUND_OUT) {
                r0.x = f2tf32f(r0.x); r0.y = f2tf32f(r0.y);
                r1.x = f2tf32f(r1.x); r1.y = f2tf32f(r1.y);
            }
            *(float2*)(C + (size_t)row * N + col)       = r0;
            *(float2*)(C + (size_t)(row + 8) * N + col) = r1;
        }
    }
}

/* fused QKV via blockIdx.z */
__global__ __launch_bounds__(128) void gemm_qkv_kernel(
    const float* __restrict__ bq, const float* __restrict__ bk,
    const float* __restrict__ bv)
{
    const float* W; const float* bias; float* C;
    if (blockIdx.z == 0)      { W = g_wq; bias = bq; C = g_q; }
    else if (blockIdx.z == 1) { W = g_wk; bias = bk; C = g_k; }
    else                      { W = g_wv; bias = bv; C = g_v; }
    gemm_body_ca<true>(g_xt, W, bias, C, MROWS, DMODEL, DMODEL,
                       blockIdx.x, blockIdx.y);
}

__global__ __launch_bounds__(128) void gemm_ca_plain_kernel(
    const float* __restrict__ A, const float* __restrict__ W,
    const float* __restrict__ bias, float* __restrict__ C,
    int M, int N, int K)
{
    gemm_body_ca<false>(A, W, bias, C, M, N, K, blockIdx.x, blockIdx.y);
}

/* ================================================================== */
/* Tensor-core flash attention (R14, unchanged): 64-key staged tiles, */
/* two 32-key compute halves, static-max softmax, cp.async staging.   */
/* Dynamic smem (88 KB): Ks[2][64][68] | Vs[2][64][72] | Ps[8][16][36]*/
/* ================================================================== */
#define QT   128
#define KVT  64
#define KHALF 32
#define KSTR 68
#define VSTR 72
#define PSTR 36
#define KS_U32 (2 * KVT * KSTR)
#define VS_U32 (2 * KVT * VSTR)
#define PS_U32 (8 * 16 * PSTR)
#define ATT_DSMB ((KS_U32 + VS_U32 + PS_U32) * 4)   /* 90112 B */

__global__ __launch_bounds__(256) void attn_mma_kernel(
    const float* __restrict__ Q, const float* __restrict__ K,
    const float* __restrict__ V, float* __restrict__ O)
{
    extern __shared__ uint32_t dsm_att[];
    uint32_t* sKs = dsm_att;
    uint32_t* sVs = dsm_att + KS_U32;
    uint32_t* sPs = dsm_att + KS_U32 + VS_U32;

    const int tid  = threadIdx.x;
    const int warp = tid >> 5;
    const int lane = tid & 31;
    const int g = lane >> 2;
    const int t = lane & 3;
    const int bh = blockIdx.y;
    const int b  = bh / NHEADS;
    const int h  = bh % NHEADS;
    const int q0 = blockIdx.x * QT + warp * 16;

    const float* qbase = Q + (size_t)(b * SEQ + q0) * DMODEL + h * HDIM;
    uint32_t qa[8][4];
#pragma unroll
    for (int kk = 0; kk < 8; kk++) {
        qa[kk][0] = f2tf32(qbase[(size_t)g       * DMODEL + kk * 8 + t    ] * SOFT_SCALE);
        qa[kk][1] = f2tf32(qbase[(size_t)(g + 8) * DMODEL + kk * 8 + t    ] * SOFT_SCALE);
        qa[kk][2] = f2tf32(qbase[(size_t)g       * DMODEL + kk * 8 + 4 + t] * SOFT_SCALE);
        qa[kk][3] = f2tf32(qbase[(size_t)(g + 8) * DMODEL + kk * 8 + 4 + t] * SOFT_SCALE);
    }

    float of[8][4];
#pragma unroll
    for (int dt = 0; dt < 8; dt++)
#pragma unroll
        for (int i = 0; i < 4; i++) of[dt][i] = 0.0f;
    float l0 = 0.0f, l1 = 0.0f;

    const float* kbase = K + (size_t)b * SEQ * DMODEL + h * HDIM;
    const float* vbase = V + (size_t)b * SEQ * DMODEL + h * HDIM;

    const int dg = (tid & 15) << 2;

    {
#pragma unroll
        for (int i = 0; i < 4; i++) {
            const int key = (tid + i * 256) >> 4;
            const size_t go = (size_t)key * DMODEL + dg;
            cp16(smem_u32(&sKs[(size_t)key * KSTR + dg]), kbase + go);
            cp16(smem_u32(&sVs[(size_t)key * VSTR + dg]), vbase + go);
        }
        cp_commit();
        cp_wait0();
        __syncthreads();
    }

    const int NTILE = SEQ / KVT;   /* 32 */
    for (int it = 0; it < NTILE; it++) {
        const int buf = it & 1;
        uint32_t* Kb = sKs + buf * KVT * KSTR;
        uint32_t* Vb = sVs + buf * KVT * VSTR;

        if (it + 1 < NTILE) {
            const int nb = buf ^ 1;
            uint32_t* Kn = sKs + nb * KVT * KSTR;
            uint32_t* Vn = sVs + nb * KVT * VSTR;
            const size_t base = (size_t)(it + 1) * KVT * DMODEL;
#pragma unroll
            for (int i = 0; i < 4; i++) {
                const int key = (tid + i * 256) >> 4;
                const size_t go = base + (size_t)key * DMODEL + dg;
                cp16(smem_u32(&Kn[(size_t)key * KSTR + dg]), kbase + go);
                cp16(smem_u32(&Vn[(size_t)key * VSTR + dg]), vbase + go);
            }
            cp_commit();
        }

#pragma unroll
        for (int hf = 0; hf < 2; hf++) {
            const uint32_t* Kh = Kb + hf * KHALF * KSTR;
            const uint32_t* Vh = Vb + hf * KHALF * VSTR;

            float sc[4][4];
#pragma unroll
            for (int nt = 0; nt < 4; nt++)
#pragma unroll
                for (int i = 0; i < 4; i++) sc[nt][i] = 0.0f;
#pragma unroll
            for (int kk = 0; kk < 8; kk++) {
#pragma unroll
                for (int nt = 0; nt < 4; nt++) {
                    const uint32_t b0 = Kh[(nt * 8 + g) * KSTR + kk * 8 + t];
                    const uint32_t b1 = Kh[(nt * 8 + g) * KSTR + kk * 8 + 4 + t];
                    mma_tf32(sc[nt], qa[kk][0], qa[kk][1], qa[kk][2], qa[kk][3], b0, b1);
                }
            }

            __syncwarp();

#pragma unroll
            for (int nt = 0; nt < 4; nt++) {
                const float p0 = exp2f(sc[nt][0]);
                const float p1 = exp2f(sc[nt][1]);
                const float p2 = exp2f(sc[nt][2]);
                const float p3 = exp2f(sc[nt][3]);
                l0 += p0 + p1;
                l1 += p2 + p3;
                uint2 lo, hi;
                lo.x = f2tf32(p0); lo.y = f2tf32(p1);
                hi.x = f2tf32(p2); hi.y = f2tf32(p3);
                *(uint2*)&sPs[(warp * 16 + g    ) * PSTR + nt * 8 + 2 * t] = lo;
                *(uint2*)&sPs[(warp * 16 + g + 8) * PSTR + nt * 8 + 2 * t] = hi;
            }
            __syncwarp();

#pragma unroll
            for (int kk = 0; kk < 4; kk++) {
                const uint32_t pa0 = sPs[(warp * 16 + g    ) * PSTR + kk * 8 + t];
                const uint32_t pa1 = sPs[(warp * 16 + g + 8) * PSTR + kk * 8 + t];
                const uint32_t pa2 = sPs[(warp * 16 + g    ) * PSTR + kk * 8 + 4 + t];
                const uint32_t pa3 = sPs[(warp * 16 + g + 8) * PSTR + kk * 8 + 4 + t];
#pragma unroll
                for (int dt = 0; dt < 8; dt++) {
                    const uint32_t b0 = Vh[(kk * 8 + t    ) * VSTR + dt * 8 + g];
                    const uint32_t b1 = Vh[(kk * 8 + 4 + t) * VSTR + dt * 8 + g];
                    mma_tf32(of[dt], pa0, pa1, pa2, pa3, b0, b1);
                }
            }
        }

        if (it + 1 < NTILE) {
            cp_wait0();
            __syncthreads();
        }
    }

    l0 += __shfl_xor_sync(0xffffffffu, l0, 1);
    l0 += __shfl_xor_sync(0xffffffffu, l0, 2);
    l1 += __shfl_xor_sync(0xffffffffu, l1, 1);
    l1 += __shfl_xor_sync(0xffffffffu, l1, 2);

    const float inv0 = 1.0f / l0;
    const float inv1 = 1.0f / l1;
    float* ob = O + (size_t)(b * SEQ + q0) * DMODEL + h * HDIM;
#pragma unroll
    for (int dt = 0; dt < 8; dt++) {
        float2 r0, r1;
        r0.x = f2tf32f(of[dt][0] * inv0); r0.y = f2tf32f(of[dt][1] * inv0);
        r1.x = f2tf32f(of[dt][2] * inv1); r1.y = f2tf32f(of[dt][3] * inv1);
        *(float2*)(ob + (size_t)g       * DMODEL + dt * 8 + 2 * t) = r0;
        *(float2*)(ob + (size_t)(g + 8) * DMODEL + dt * 8 + 2 * t) = r1;
    }
}

/* ------------------------------------------------------------------ */
extern "C" void kernel_launch(void* const* d_in, const int* in_sizes, int n_in,
                              void* d_out, int out_size)
{
    const float* x  = (const float*)d_in[0];
    const float* Wq = (const float*)d_in[1];
    const float* bq = (const float*)d_in[2];
    const float* Wk = (const float*)d_in[3];
    const float* bk = (const float*)d_in[4];
    const float* Wv = (const float*)d_in[5];
    const float* bv = (const float*)d_in[6];
    const float* Wo = (const float*)d_in[7];
    const float* bo = (const float*)d_in[8];
    float* out = (float*)d_out;

    float *q, *k, *v, *att, *wo;
    cudaGetSymbolAddress((void**)&q,   g_q);
    cudaGetSymbolAddress((void**)&k,   g_k);
    cudaGetSymbolAddress((void**)&v,   g_v);
    cudaGetSymbolAddress((void**)&att, g_att);
    cudaGetSymbolAddress((void**)&wo,  g_wo);

    cudaFuncSetAttribute(attn_mma_kernel,
        cudaFuncAttributeMaxDynamicSharedMemorySize, ATT_DSMB);

    /* prep: round x + all W to tf32 values */
    dim3 gprep(DMODEL * DMODEL / 4 / 256, 8);   /* (1024, 8) */
    round_prep_kernel<<<gprep, 256>>>(x, Wq, Wk, Wv, Wo);

    /* fused QKV: (8, 32, 3) = 768 CTAs, 128 threads each */
    dim3 gqkv(DMODEL / GN, MROWS / GM, 3);
    gemm_qkv_kernel<<<gqkv, 128>>>(bq, bk, bv);

    dim3 gattn(SEQ / QT, BATCH * NHEADS);  /* (16, 32) */
    attn_mma_kernel<<<gattn, 256, ATT_DSMB>>>(q, k, v, att);

    dim3 gproj(DMODEL / GN, MROWS / GM);   /* (8, 32) = 256 CTAs */
    gemm_ca_plain_kernel<<<gproj, 128>>>(att, wo, bo, out, MROWS, DMODEL, DMODEL);
}

// round 17
// speedup vs baseline: 1.0650x; 1.0448x over previous
#include <cuda_runtime.h>
#include <math.h>
#include <stdint.h>

#define BATCH   2
#define SEQ     2048
#define DMODEL  1024
#define NHEADS  16
#define HDIM    64
#define MROWS   (BATCH * SEQ)   /* 4096 */
#define SOFT_SCALE 0.18033688011112042f   /* 0.125 * log2(e) */

/* Scratch (allocation-free rule: __device__ globals). */
static __device__ float g_q[MROWS * DMODEL];
static __device__ float g_k[MROWS * DMODEL];
static __device__ float g_v[MROWS * DMODEL];
static __device__ float g_att[MROWS * DMODEL];
static __device__ float g_xt[MROWS * DMODEL];           /* tf32-rounded x  */
static __device__ float g_wq[DMODEL * DMODEL];
static __device__ float g_wk[DMODEL * DMODEL];
static __device__ float g_wv[DMODEL * DMODEL];
static __device__ float g_wo[DMODEL * DMODEL];

__device__ __forceinline__ uint32_t f2tf32(float f) {
    uint32_t r;
    asm("cvt.rna.tf32.f32 %0, %1;" : "=r"(r) : "f"(f));
    return r;
}
__device__ __forceinline__ float f2tf32f(float f) {
    return __uint_as_float(f2tf32(f));
}

__device__ __forceinline__ void mma_tf32(float c[4],
    uint32_t a0, uint32_t a1, uint32_t a2, uint32_t a3,
    uint32_t b0, uint32_t b1)
{
    asm volatile(
        "mma.sync.aligned.m16n8k8.row.col.f32.tf32.tf32.f32 "
        "{%0,%1,%2,%3}, {%4,%5,%6,%7}, {%8,%9}, {%0,%1,%2,%3};"
        : "+f"(c[0]), "+f"(c[1]), "+f"(c[2]), "+f"(c[3])
        : "r"(a0), "r"(a1), "r"(a2), "r"(a3), "r"(b0), "r"(b1));
}

__device__ __forceinline__ void cp16(uint32_t dst_smem, const void* src) {
    asm volatile("cp.async.cg.shared.global [%0], [%1], 16;"
                 :: "r"(dst_smem), "l"(src));
}
__device__ __forceinline__ void cp_commit() { asm volatile("cp.async.commit_group;"); }
__device__ __forceinline__ void cp_wait0()  { asm volatile("cp.async.wait_group 0;"); }
__device__ __forceinline__ uint32_t smem_u32(const void* p) {
    return (uint32_t)__cvta_generic_to_shared(p);
}

/* ================================================================== */
/* Prep: round x and all W to tf32 values (exact mma inputs later).   */
/* ================================================================== */
__global__ __launch_bounds__(256) void round_prep_kernel(
    const float* __restrict__ x,
    const float* __restrict__ Wq, const float* __restrict__ Wk,
    const float* __restrict__ Wv, const float* __restrict__ Wo)
{
    const int seg = blockIdx.y;
    const float* src;
    float* dst;
    const int M1 = DMODEL * DMODEL;   /* 1M floats */
    if (seg < 4)      { src = x  + (size_t)seg * M1; dst = g_xt + (size_t)seg * M1; }
    else if (seg == 4){ src = Wq; dst = g_wq; }
    else if (seg == 5){ src = Wk; dst = g_wk; }
    else if (seg == 6){ src = Wv; dst = g_wv; }
    else              { src = Wo; dst = g_wo; }

    const int idx = blockIdx.x * blockDim.x + threadIdx.x;
    float4 v = ((const float4*)src)[idx];
    v.x = f2tf32f(v.x); v.y = f2tf32f(v.y);
    v.z = f2tf32f(v.z); v.w = f2tf32f(v.w);
    ((float4*)dst)[idx] = v;
}

/* ================================================================== */
/* TF32 GEMM v8: R8 shape (CTA 128x256, 256 thr, warp 64x64) but      */
/* GK=32 -> 32 loop iterations instead of 64: half the cp.async       */
/* waits + barriers per unit MMA (the lever that won in R14's attn).  */
/* ASTR=36: af banks 4g+t distinct. BSTR=264: bf banks 8(kk+t)+n0+g   */
/* distinct. All cp.async dsts 16B-aligned. Dynamic smem 104448 B.    */
/* ================================================================== */
#define GM 128
#define GN 256
#define GK 32
#define ASTR 36
#define BSTR 264
#define A_STAGE (GM * ASTR)                 /* 4608 floats */
#define B_STAGE (GK * BSTR)                 /* 8448 floats */
#define GEMM_DSMB (2 * (A_STAGE + B_STAGE) * 4)   /* 104448 B */

template<bool ROUND_OUT>
__device__ __forceinline__ void gemm_body_ca(
    const float* __restrict__ A, const float* __restrict__ W,
    const float* __restrict__ bias, float* __restrict__ C,
    int M, int N, int K, int bx, int by)
{
    extern __shared__ float dsm[];
    float* AsB = dsm;                       /* [2][GM][ASTR] */
    float* BsB = dsm + 2 * A_STAGE;         /* [2][GK][BSTR] */

    const int tid  = threadIdx.x;
    const int warp = tid >> 5;
    const int lane = tid & 31;
    const int g = lane >> 2;
    const int t = lane & 3;

    const int wm = (warp & 1) * 64;
    const int wn = (warp >> 1) * 64;

    const int brow0 = by * GM;
    const int bcol0 = bx * GN;

    /* cp.async maps (256 thr):
       A 128x32 = 1024 chunks -> 4/thread: rows (tid>>3)+32i, chunk (tid&7)
       B 32x256 = 2048 chunks -> 8/thread: rows (tid>>6)+4j, col (tid&63)*4 */
    const int arow = tid >> 3;            /* 0..31 */
    const int ka   = (tid & 7) * 4;       /* 0..28 */
    const int brow = tid >> 6;            /* 0..3  */
    const int colb = (tid & 63) * 4;      /* 0..252 */

    float acc[4][8][4];
#pragma unroll
    for (int mt = 0; mt < 4; mt++)
#pragma unroll
        for (int nt = 0; nt < 8; nt++)
#pragma unroll
            for (int i = 0; i < 4; i++) acc[mt][nt][i] = 0.0f;

    const float* Abase = A + (size_t)brow0 * K;
    const float* Wbase = W + bcol0;

    /* prologue: tile 0 */
    {
        float* As0 = AsB;
        float* Bs0 = BsB;
#pragma unroll
        for (int i = 0; i < 4; i++) {
            const int r = arow + i * 32;
            cp16(smem_u32(As0 + r * ASTR + ka), Abase + (size_t)r * K + ka);
        }
#pragma unroll
        for (int j = 0; j < 8; j++) {
            const int r = brow + j * 4;
            cp16(smem_u32(Bs0 + r * BSTR + colb), Wbase + (size_t)r * N + colb);
        }
        cp_commit();
        cp_wait0();
        __syncthreads();
    }

    const int NIT = K / GK;   /* 32 */
    for (int it = 0; it < NIT; it++) {
        const int buf = it & 1;
        const float* Asb = AsB + buf * A_STAGE;
        const float* Bsb = BsB + buf * B_STAGE;

        if (it + 1 < NIT) {
            const int nb = buf ^ 1;
            const int k0 = (it + 1) * GK;
            float* Asn = AsB + nb * A_STAGE;
            float* Bsn = BsB + nb * B_STAGE;
#pragma unroll
            for (int i = 0; i < 4; i++) {
                const int r = arow + i * 32;
                cp16(smem_u32(Asn + r * ASTR + ka), Abase + (size_t)r * K + k0 + ka);
            }
#pragma unroll
            for (int j = 0; j < 8; j++) {
                const int r = brow + j * 4;
                cp16(smem_u32(Bsn + r * BSTR + colb), Wbase + (size_t)(k0 + r) * N + colb);
            }
            cp_commit();
        }

#pragma unroll
        for (int kk = 0; kk < GK; kk += 8) {
            uint32_t af[4][4];
            uint32_t bf[8][2];
#pragma unroll
            for (int mt = 0; mt < 4; mt++) {
                const int m0 = wm + mt * 16;
                af[mt][0] = __float_as_uint(Asb[(m0 + g    ) * ASTR + kk + t    ]);
                af[mt][1] = __float_as_uint(Asb[(m0 + 8 + g) * ASTR + kk + t    ]);
                af[mt][2] = __float_as_uint(Asb[(m0 + g    ) * ASTR + kk + 4 + t]);
                af[mt][3] = __float_as_uint(Asb[(m0 + 8 + g) * ASTR + kk + 4 + t]);
            }
#pragma unroll
            for (int nt = 0; nt < 8; nt++) {
                const int n0 = wn + nt * 8;
                bf[nt][0] = __float_as_uint(Bsb[(kk + t    ) * BSTR + n0 + g]);
                bf[nt][1] = __float_as_uint(Bsb[(kk + 4 + t) * BSTR + n0 + g]);
            }
#pragma unroll
            for (int mt = 0; mt < 4; mt++)
#pragma unroll
                for (int nt = 0; nt < 8; nt++)
                    mma_tf32(acc[mt][nt],
                             af[mt][0], af[mt][1], af[mt][2], af[mt][3],
                             bf[nt][0], bf[nt][1]);
        }

        if (it + 1 < NIT) {
            cp_wait0();
            __syncthreads();
        }
    }

    /* epilogue */
#pragma unroll
    for (int mt = 0; mt < 4; mt++) {
#pragma unroll
        for (int nt = 0; nt < 8; nt++) {
            const int row = brow0 + wm + mt * 16 + g;
            const int col = bcol0 + wn + nt * 8 + t * 2;
            const float b0 = bias[col];
            const float b1 = bias[col + 1];
            float2 r0, r1;
            r0.x = acc[mt][nt][0] + b0;
            r0.y = acc[mt][nt][1] + b1;
            r1.x = acc[mt][nt][2] + b0;
            r1.y = acc[mt][nt][3] + b1;
            if (ROUND_OUT) {
                r0.x = f2tf32f(r0.x); r0.y = f2tf32f(r0.y);
                r1.x = f2tf32f(r1.x); r1.y = f2tf32f(r1.y);
            }
            *(float2*)(C + (size_t)row * N + col)       = r0;
            *(float2*)(C + (size_t)(row + 8) * N + col) = r1;
        }
    }
}

/* fused QKV via blockIdx.z */
__global__ __launch_bounds__(256) void gemm_qkv_kernel(
    const float* __restrict__ bq, const float* __restrict__ bk,
    const float* __restrict__ bv)
{
    const float* W; const float* bias; float* C;
    if (blockIdx.z == 0)      { W = g_wq; bias = bq; C = g_q; }
    else if (blockIdx.z == 1) { W = g_wk; bias = bk; C = g_k; }
    else                      { W = g_wv; bias = bv; C = g_v; }
    gemm_body_ca<true>(g_xt, W, bias, C, MROWS, DMODEL, DMODEL,
                       blockIdx.x, blockIdx.y);
}

__global__ __launch_bounds__(256) void gemm_ca_plain_kernel(
    const float* __restrict__ A, const float* __restrict__ W,
    const float* __restrict__ bias, float* __restrict__ C,
    int M, int N, int K)
{
    gemm_body_ca<false>(A, W, bias, C, M, N, K, blockIdx.x, blockIdx.y);
}

/* ================================================================== */
/* Tensor-core flash attention (R14, unchanged): 64-key staged tiles, */
/* two 32-key compute halves, static-max softmax, cp.async staging.   */
/* Dynamic smem (88 KB): Ks[2][64][68] | Vs[2][64][72] | Ps[8][16][36]*/
/* ================================================================== */
#define QT   128
#define KVT  64
#define KHALF 32
#define KSTR 68
#define VSTR 72
#define PSTR 36
#define KS_U32 (2 * KVT * KSTR)
#define VS_U32 (2 * KVT * VSTR)
#define PS_U32 (8 * 16 * PSTR)
#define ATT_DSMB ((KS_U32 + VS_U32 + PS_U32) * 4)   /* 90112 B */

__global__ __launch_bounds__(256) void attn_mma_kernel(
    const float* __restrict__ Q, const float* __restrict__ K,
    const float* __restrict__ V, float* __restrict__ O)
{
    extern __shared__ uint32_t dsm_att[];
    uint32_t* sKs = dsm_att;
    uint32_t* sVs = dsm_att + KS_U32;
    uint32_t* sPs = dsm_att + KS_U32 + VS_U32;

    const int tid  = threadIdx.x;
    const int warp = tid >> 5;
    const int lane = tid & 31;
    const int g = lane >> 2;
    const int t = lane & 3;
    const int bh = blockIdx.y;
    const int b  = bh / NHEADS;
    const int h  = bh % NHEADS;
    const int q0 = blockIdx.x * QT + warp * 16;

    const float* qbase = Q + (size_t)(b * SEQ + q0) * DMODEL + h * HDIM;
    uint32_t qa[8][4];
#pragma unroll
    for (int kk = 0; kk < 8; kk++) {
        qa[kk][0] = f2tf32(qbase[(size_t)g       * DMODEL + kk * 8 + t    ] * SOFT_SCALE);
        qa[kk][1] = f2tf32(qbase[(size_t)(g + 8) * DMODEL + kk * 8 + t    ] * SOFT_SCALE);
        qa[kk][2] = f2tf32(qbase[(size_t)g       * DMODEL + kk * 8 + 4 + t] * SOFT_SCALE);
        qa[kk][3] = f2tf32(qbase[(size_t)(g + 8) * DMODEL + kk * 8 + 4 + t] * SOFT_SCALE);
    }

    float of[8][4];
#pragma unroll
    for (int dt = 0; dt < 8; dt++)
#pragma unroll
        for (int i = 0; i < 4; i++) of[dt][i] = 0.0f;
    float l0 = 0.0f, l1 = 0.0f;

    const float* kbase = K + (size_t)b * SEQ * DMODEL + h * HDIM;
    const float* vbase = V + (size_t)b * SEQ * DMODEL + h * HDIM;

    const int dg = (tid & 15) << 2;

    {
#pragma unroll
        for (int i = 0; i < 4; i++) {
            const int key = (tid + i * 256) >> 4;
            const size_t go = (size_t)key * DMODEL + dg;
            cp16(smem_u32(&sKs[(size_t)key * KSTR + dg]), kbase + go);
            cp16(smem_u32(&sVs[(size_t)key * VSTR + dg]), vbase + go);
        }
        cp_commit();
        cp_wait0();
        __syncthreads();
    }

    const int NTILE = SEQ / KVT;   /* 32 */
    for (int it = 0; it < NTILE; it++) {
        const int buf = it & 1;
        uint32_t* Kb = sKs + buf * KVT * KSTR;
        uint32_t* Vb = sVs + buf * KVT * VSTR;

        if (it + 1 < NTILE) {
            const int nb = buf ^ 1;
            uint32_t* Kn = sKs + nb * KVT * KSTR;
            uint32_t* Vn = sVs + nb * KVT * VSTR;
            const size_t base = (size_t)(it + 1) * KVT * DMODEL;
#pragma unroll
            for (int i = 0; i < 4; i++) {
                const int key = (tid + i * 256) >> 4;
                const size_t go = base + (size_t)key * DMODEL + dg;
                cp16(smem_u32(&Kn[(size_t)key * KSTR + dg]), kbase + go);
                cp16(smem_u32(&Vn[(size_t)key * VSTR + dg]), vbase + go);
            }
            cp_commit();
        }

#pragma unroll
        for (int hf = 0; hf < 2; hf++) {
            const uint32_t* Kh = Kb + hf * KHALF * KSTR;
            const uint32_t* Vh = Vb + hf * KHALF * VSTR;

            float sc[4][4];
#pragma unroll
            for (int nt = 0; nt < 4; nt++)
#pragma unroll
                for (int i = 0; i < 4; i++) sc[nt][i] = 0.0f;
#pragma unroll
            for (int kk = 0; kk < 8; kk++) {
#pragma unroll
                for (int nt = 0; nt < 4; nt++) {
                    const uint32_t b0 = Kh[(nt * 8 + g) * KSTR + kk * 8 + t];
                    const uint32_t b1 = Kh[(nt * 8 + g) * KSTR + kk * 8 + 4 + t];
                    mma_tf32(sc[nt], qa[kk][0], qa[kk][1], qa[kk][2], qa[kk][3], b0, b1);
                }
            }

            __syncwarp();

#pragma unroll
            for (int nt = 0; nt < 4; nt++) {
                const float p0 = exp2f(sc[nt][0]);
                const float p1 = exp2f(sc[nt][1]);
                const float p2 = exp2f(sc[nt][2]);
                const float p3 = exp2f(sc[nt][3]);
                l0 += p0 + p1;
                l1 += p2 + p3;
                uint2 lo, hi;
                lo.x = f2tf32(p0); lo.y = f2tf32(p1);
                hi.x = f2tf32(p2); hi.y = f2tf32(p3);
                *(uint2*)&sPs[(warp * 16 + g    ) * PSTR + nt * 8 + 2 * t] = lo;
                *(uint2*)&sPs[(warp * 16 + g + 8) * PSTR + nt * 8 + 2 * t] = hi;
            }
            __syncwarp();

#pragma unroll
            for (int kk = 0; kk < 4; kk++) {
                const uint32_t pa0 = sPs[(warp * 16 + g    ) * PSTR + kk * 8 + t];
                const uint32_t pa1 = sPs[(warp * 16 + g + 8) * PSTR + kk * 8 + t];
                const uint32_t pa2 = sPs[(warp * 16 + g    ) * PSTR + kk * 8 + 4 + t];
                const uint32_t pa3 = sPs[(warp * 16 + g + 8) * PSTR + kk * 8 + 4 + t];
#pragma unroll
                for (int dt = 0; dt < 8; dt++) {
                    const uint32_t b0 = Vh[(kk * 8 + t    ) * VSTR + dt * 8 + g];
                    const uint32_t b1 = Vh[(kk * 8 + 4 + t) * VSTR + dt * 8 + g];
                    mma_tf32(of[dt], pa0, pa1, pa2, pa3, b0, b1);
                }
            }
        }

        if (it + 1 < NTILE) {
            cp_wait0();
            __syncthreads();
        }
    }

    l0 += __shfl_xor_sync(0xffffffffu, l0, 1);
    l0 += __shfl_xor_sync(0xffffffffu, l0, 2);
    l1 += __shfl_xor_sync(0xffffffffu, l1, 1);
    l1 += __shfl_xor_sync(0xffffffffu, l1, 2);

    const float inv0 = 1.0f / l0;
    const float inv1 = 1.0f / l1;
    float* ob = O + (size_t)(b * SEQ + q0) * DMODEL + h * HDIM;
#pragma unroll
    for (int dt = 0; dt < 8; dt++) {
        float2 r0, r1;
        r0.x = f2tf32f(of[dt][0] * inv0); r0.y = f2tf32f(of[dt][1] * inv0);
        r1.x = f2tf32f(of[dt][2] * inv1); r1.y = f2tf32f(of[dt][3] * inv1);
        *(float2*)(ob + (size_t)g       * DMODEL + dt * 8 + 2 * t) = r0;
        *(float2*)(ob + (size_t)(g + 8) * DMODEL + dt * 8 + 2 * t) = r1;
    }
}

/* ------------------------------------------------------------------ */
extern "C" void kernel_launch(void* const* d_in, const int* in_sizes, int n_in,
                              void* d_out, int out_size)
{
    const float* x  = (const float*)d_in[0];
    const float* Wq = (const float*)d_in[1];
    const float* bq = (const float*)d_in[2];
    const float* Wk = (const float*)d_in[3];
    const float* bk = (const float*)d_in[4];
    const float* Wv = (const float*)d_in[5];
    const float* bv = (const float*)d_in[6];
    const float* Wo = (const float*)d_in[7];
    const float* bo = (const float*)d_in[8];
    float* out = (float*)d_out;

    float *q, *k, *v, *att, *wo;
    cudaGetSymbolAddress((void**)&q,   g_q);
    cudaGetSymbolAddress((void**)&k,   g_k);
    cudaGetSymbolAddress((void**)&v,   g_v);
    cudaGetSymbolAddress((void**)&att, g_att);
    cudaGetSymbolAddress((void**)&wo,  g_wo);

    cudaFuncSetAttribute(gemm_qkv_kernel,
        cudaFuncAttributeMaxDynamicSharedMemorySize, GEMM_DSMB);
    cudaFuncSetAttribute(gemm_ca_plain_kernel,
        cudaFuncAttributeMaxDynamicSharedMemorySize, GEMM_DSMB);
    cudaFuncSetAttribute(attn_mma_kernel,
        cudaFuncAttributeMaxDynamicSharedMemorySize, ATT_DSMB);

    /* prep: round x + all W to tf32 values */
    dim3 gprep(DMODEL * DMODEL / 4 / 256, 8);   /* (1024, 8) */
    round_prep_kernel<<<gprep, 256>>>(x, Wq, Wk, Wv, Wo);

    /* fused QKV: (4, 32, 3) = 384 CTAs */
    dim3 gqkv(DMODEL / GN, MROWS / GM, 3);
    gemm_qkv_kernel<<<gqkv, 256, GEMM_DSMB>>>(bq, bk, bv);

    dim3 gattn(SEQ / QT, BATCH * NHEADS);  /* (16, 32) */
    attn_mma_kernel<<<gattn, 256, ATT_DSMB>>>(q, k, v, att);

    dim3 gproj(DMODEL / GN, MROWS / GM);   /* (4, 32) = 128 CTAs */
    gemm_ca_plain_kernel<<<gproj, 256, GEMM_DSMB>>>(att, wo, bo, out, MROWS, DMODEL, DMODEL);
}